// round 2
// baseline (speedup 1.0000x reference)
#include <cuda_runtime.h>

// RK4 over tiny MLP (3 -> 8 -> 1, ReLU), per-row, fp32.
// y0' = f(y0, y1, y2); y1,y2 constant per row across stages.
// Key transform: hidden pre-activation = w0_j*y0_stage + c_j where
//   c_j = b1_j + w1_j*y1 + w2_j*y2  (precomputed once per row).
// Hidden/output matvecs use Blackwell packed fma.rn.f32x2 (2 units per op).

#define DT       0.25f
#define HALF_DT  0.125f
#define DT6      (0.25f / 6.0f)

__device__ __forceinline__ float2 ffma2(float2 a, float2 b, float2 c) {
    float2 d;
    asm("{\n\t"
        ".reg .b64 ra, rb, rc, rd;\n\t"
        "mov.b64 ra, {%2, %3};\n\t"
        "mov.b64 rb, {%4, %5};\n\t"
        "mov.b64 rc, {%6, %7};\n\t"
        "fma.rn.f32x2 rd, ra, rb, rc;\n\t"
        "mov.b64 {%0, %1}, rd;\n\t"
        "}"
        : "=f"(d.x), "=f"(d.y)
        : "f"(a.x), "f"(a.y), "f"(b.x), "f"(b.y), "f"(c.x), "f"(c.y));
    return d;
}

struct Weights {
    float2 w0[4];   // y0 coefficients, packed (unit 2k, 2k+1)
    float2 w1[4];   // y1 coefficients
    float2 w2[4];   // y2 coefficients
    float2 bb[4];   // b1 packed
    float2 v[4];    // W2 packed
    float  b2;
};

// One RK4 stage evaluation: k = b2 + sum_j v_j * relu(w0_j*y0s + c_j)
__device__ __forceinline__ float mlp_eval(const Weights& W, const float2 (&C)[4], float y0s) {
    float2 ys = make_float2(y0s, y0s);
    float2 acc = make_float2(W.b2, 0.0f);
#pragma unroll
    for (int k = 0; k < 4; k++) {
        float2 t = ffma2(W.w0[k], ys, C[k]);
        t.x = fmaxf(t.x, 0.0f);      // FMNMX -> alu pipe (overlaps fma pipe)
        t.y = fmaxf(t.y, 0.0f);
        acc = ffma2(W.v[k], t, acc);
    }
    return acc.x + acc.y;
}

__device__ __forceinline__ float rk4_row(const Weights& W, float y0, float y1, float y2) {
    // Per-row constants c_j = b1_j + w1_j*y1 + w2_j*y2
    float2 C[4];
    float2 y1b = make_float2(y1, y1);
    float2 y2b = make_float2(y2, y2);
#pragma unroll
    for (int k = 0; k < 4; k++)
        C[k] = ffma2(W.w2[k], y2b, ffma2(W.w1[k], y1b, W.bb[k]));

    float k1 = mlp_eval(W, C, y0);
    float k2 = mlp_eval(W, C, fmaf(HALF_DT, k1, y0));
    float k3 = mlp_eval(W, C, fmaf(HALF_DT, k2, y0));
    float k4 = mlp_eval(W, C, fmaf(DT, k3, y0));

    float s = fmaf(2.0f, k2 + k3, k1 + k4);
    return fmaf(DT6, s, y0);
}

__global__ void __launch_bounds__(256)
node_rk4_kernel(const float* __restrict__ x,
                const float* __restrict__ W1,
                const float* __restrict__ b1,
                const float* __restrict__ W2,
                const float* __restrict__ b2,
                float* __restrict__ out,
                int ngroups)   // ngroups = rows/4
{
    // ---- Load weights (11 vector LDGs, all-lane-uniform -> L1 broadcast) ----
    const float4* W14 = reinterpret_cast<const float4*>(W1);
    float4 wA = __ldg(&W14[0]);   // W1[0..3]   a0_0 a1_0 a2_0 a0_1
    float4 wB = __ldg(&W14[1]);   // W1[4..7]   a1_1 a2_1 a0_2 a1_2
    float4 wC = __ldg(&W14[2]);   // W1[8..11]  a2_2 a0_3 a1_3 a2_3
    float4 wD = __ldg(&W14[3]);   // W1[12..15] a0_4 a1_4 a2_4 a0_5
    float4 wE = __ldg(&W14[4]);   // W1[16..19] a1_5 a2_5 a0_6 a1_6
    float4 wF = __ldg(&W14[5]);   // W1[20..23] a2_6 a0_7 a1_7 a2_7
    const float4* b14 = reinterpret_cast<const float4*>(b1);
    float4 bA = __ldg(&b14[0]);
    float4 bB = __ldg(&b14[1]);
    const float4* W24 = reinterpret_cast<const float4*>(W2);
    float4 vA = __ldg(&W24[0]);
    float4 vB = __ldg(&W24[1]);

    Weights W;
    W.w0[0] = make_float2(wA.x, wA.w);
    W.w0[1] = make_float2(wB.z, wC.y);
    W.w0[2] = make_float2(wD.x, wD.w);
    W.w0[3] = make_float2(wE.z, wF.y);

    W.w1[0] = make_float2(wA.y, wB.x);
    W.w1[1] = make_float2(wB.w, wC.z);
    W.w1[2] = make_float2(wD.y, wE.x);
    W.w1[3] = make_float2(wE.w, wF.z);

    W.w2[0] = make_float2(wA.z, wB.y);
    W.w2[1] = make_float2(wC.x, wC.w);
    W.w2[2] = make_float2(wD.z, wE.y);
    W.w2[3] = make_float2(wF.x, wF.w);

    W.bb[0] = make_float2(bA.x, bA.y);
    W.bb[1] = make_float2(bA.z, bA.w);
    W.bb[2] = make_float2(bB.x, bB.y);
    W.bb[3] = make_float2(bB.z, bB.w);

    W.v[0] = make_float2(vA.x, vA.y);
    W.v[1] = make_float2(vA.z, vA.w);
    W.v[2] = make_float2(vB.x, vB.y);
    W.v[3] = make_float2(vB.z, vB.w);

    W.b2 = __ldg(b2);

    const float4* x4   = reinterpret_cast<const float4*>(x);
    float4*       out4 = reinterpret_cast<float4*>(out);

    int g = blockIdx.x * blockDim.x + threadIdx.x;
    const int stride = gridDim.x * blockDim.x;

#pragma unroll
    for (int it = 0; it < 4; it++, g += stride) {
        if (g < ngroups) {
            // 4 rows = 12 floats = 3 coalesced float4 loads
            float4 fa = __ldg(&x4[3 * g + 0]);
            float4 fb = __ldg(&x4[3 * g + 1]);
            float4 fc = __ldg(&x4[3 * g + 2]);

            float r0 = rk4_row(W, fa.x, fa.y, fa.z);
            float r1 = rk4_row(W, fa.w, fb.x, fb.y);
            float r2 = rk4_row(W, fb.z, fb.w, fc.x);
            float r3 = rk4_row(W, fc.y, fc.z, fc.w);

            out4[g] = make_float4(r0, r1, r2, r3);
        }
    }
}

extern "C" void kernel_launch(void* const* d_in, const int* in_sizes, int n_in,
                              void* d_out, int out_size)
{
    const float* x  = (const float*)d_in[0];
    const float* W1 = (const float*)d_in[1];
    const float* b1 = (const float*)d_in[2];
    const float* W2 = (const float*)d_in[3];
    const float* b2 = (const float*)d_in[4];
    float* out = (float*)d_out;

    int rows    = in_sizes[0] / 3;       // 8388608
    int ngroups = rows / 4;              // rows is a multiple of 4 here
    int total_threads = (ngroups + 3) / 4;   // 4 groups (16 rows) per thread
    int block = 256;
    int grid  = (total_threads + block - 1) / block;

    node_rk4_kernel<<<grid, block>>>(x, W1, b1, W2, b2, out, ngroups);
}

// round 3
// speedup vs baseline: 1.0026x; 1.0026x over previous
#include <cuda_runtime.h>

// RK4 over tiny MLP (3 -> 8 -> 1, ReLU), per-row, fp32.
// y0' = f(y0, y1, y2); y1,y2 constant per row across stages.
// Key transform: hidden pre-activation = w0_j*y0_stage + c_j where
//   c_j = b1_j + w1_j*y1 + w2_j*y2  (precomputed once per row).
// Hidden/output matvecs use Blackwell packed fma.rn.f32x2 (2 units per op).

#define DT       0.25f
#define HALF_DT  0.125f
#define DT6      (0.25f / 6.0f)

__device__ __forceinline__ float2 ffma2(float2 a, float2 b, float2 c) {
    float2 d;
    asm("{\n\t"
        ".reg .b64 ra, rb, rc, rd;\n\t"
        "mov.b64 ra, {%2, %3};\n\t"
        "mov.b64 rb, {%4, %5};\n\t"
        "mov.b64 rc, {%6, %7};\n\t"
        "fma.rn.f32x2 rd, ra, rb, rc;\n\t"
        "mov.b64 {%0, %1}, rd;\n\t"
        "}"
        : "=f"(d.x), "=f"(d.y)
        : "f"(a.x), "f"(a.y), "f"(b.x), "f"(b.y), "f"(c.x), "f"(c.y));
    return d;
}

struct Weights {
    float2 w0[4];   // y0 coefficients, packed (unit 2k, 2k+1)
    float2 w1[4];   // y1 coefficients
    float2 w2[4];   // y2 coefficients
    float2 bb[4];   // b1 packed
    float2 v[4];    // W2 packed
    float  b2;
};

// One RK4 stage evaluation: k = b2 + sum_j v_j * relu(w0_j*y0s + c_j)
__device__ __forceinline__ float mlp_eval(const Weights& W, const float2 (&C)[4], float y0s) {
    float2 ys = make_float2(y0s, y0s);
    float2 acc = make_float2(W.b2, 0.0f);
#pragma unroll
    for (int k = 0; k < 4; k++) {
        float2 t = ffma2(W.w0[k], ys, C[k]);
        t.x = fmaxf(t.x, 0.0f);      // FMNMX -> alu pipe (overlaps fma pipe)
        t.y = fmaxf(t.y, 0.0f);
        acc = ffma2(W.v[k], t, acc);
    }
    return acc.x + acc.y;
}

__device__ __forceinline__ float rk4_row(const Weights& W, float y0, float y1, float y2) {
    // Per-row constants c_j = b1_j + w1_j*y1 + w2_j*y2
    float2 C[4];
    float2 y1b = make_float2(y1, y1);
    float2 y2b = make_float2(y2, y2);
#pragma unroll
    for (int k = 0; k < 4; k++)
        C[k] = ffma2(W.w2[k], y2b, ffma2(W.w1[k], y1b, W.bb[k]));

    float k1 = mlp_eval(W, C, y0);
    float k2 = mlp_eval(W, C, fmaf(HALF_DT, k1, y0));
    float k3 = mlp_eval(W, C, fmaf(HALF_DT, k2, y0));
    float k4 = mlp_eval(W, C, fmaf(DT, k3, y0));

    float s = fmaf(2.0f, k2 + k3, k1 + k4);
    return fmaf(DT6, s, y0);
}

__global__ void __launch_bounds__(256)
node_rk4_kernel(const float* __restrict__ x,
                const float* __restrict__ W1,
                const float* __restrict__ b1,
                const float* __restrict__ W2,
                const float* __restrict__ b2,
                float* __restrict__ out,
                int ngroups)   // ngroups = rows/4
{
    // ---- Load weights (11 vector LDGs, all-lane-uniform -> L1 broadcast) ----
    const float4* W14 = reinterpret_cast<const float4*>(W1);
    float4 wA = __ldg(&W14[0]);   // W1[0..3]   a0_0 a1_0 a2_0 a0_1
    float4 wB = __ldg(&W14[1]);   // W1[4..7]   a1_1 a2_1 a0_2 a1_2
    float4 wC = __ldg(&W14[2]);   // W1[8..11]  a2_2 a0_3 a1_3 a2_3
    float4 wD = __ldg(&W14[3]);   // W1[12..15] a0_4 a1_4 a2_4 a0_5
    float4 wE = __ldg(&W14[4]);   // W1[16..19] a1_5 a2_5 a0_6 a1_6
    float4 wF = __ldg(&W14[5]);   // W1[20..23] a2_6 a0_7 a1_7 a2_7
    const float4* b14 = reinterpret_cast<const float4*>(b1);
    float4 bA = __ldg(&b14[0]);
    float4 bB = __ldg(&b14[1]);
    const float4* W24 = reinterpret_cast<const float4*>(W2);
    float4 vA = __ldg(&W24[0]);
    float4 vB = __ldg(&W24[1]);

    Weights W;
    W.w0[0] = make_float2(wA.x, wA.w);
    W.w0[1] = make_float2(wB.z, wC.y);
    W.w0[2] = make_float2(wD.x, wD.w);
    W.w0[3] = make_float2(wE.z, wF.y);

    W.w1[0] = make_float2(wA.y, wB.x);
    W.w1[1] = make_float2(wB.w, wC.z);
    W.w1[2] = make_float2(wD.y, wE.x);
    W.w1[3] = make_float2(wE.w, wF.z);

    W.w2[0] = make_float2(wA.z, wB.y);
    W.w2[1] = make_float2(wC.x, wC.w);
    W.w2[2] = make_float2(wD.z, wE.y);
    W.w2[3] = make_float2(wF.x, wF.w);

    W.bb[0] = make_float2(bA.x, bA.y);
    W.bb[1] = make_float2(bA.z, bA.w);
    W.bb[2] = make_float2(bB.x, bB.y);
    W.bb[3] = make_float2(bB.z, bB.w);

    W.v[0] = make_float2(vA.x, vA.y);
    W.v[1] = make_float2(vA.z, vA.w);
    W.v[2] = make_float2(vB.x, vB.y);
    W.v[3] = make_float2(vB.z, vB.w);

    W.b2 = __ldg(b2);

    const float4* x4   = reinterpret_cast<const float4*>(x);
    float4*       out4 = reinterpret_cast<float4*>(out);

    int g = blockIdx.x * blockDim.x + threadIdx.x;
    const int stride = gridDim.x * blockDim.x;

#pragma unroll
    for (int it = 0; it < 4; it++, g += stride) {
        if (g < ngroups) {
            // 4 rows = 12 floats = 3 coalesced float4 loads
            float4 fa = __ldg(&x4[3 * g + 0]);
            float4 fb = __ldg(&x4[3 * g + 1]);
            float4 fc = __ldg(&x4[3 * g + 2]);

            float r0 = rk4_row(W, fa.x, fa.y, fa.z);
            float r1 = rk4_row(W, fa.w, fb.x, fb.y);
            float r2 = rk4_row(W, fb.z, fb.w, fc.x);
            float r3 = rk4_row(W, fc.y, fc.z, fc.w);

            out4[g] = make_float4(r0, r1, r2, r3);
        }
    }
}

extern "C" void kernel_launch(void* const* d_in, const int* in_sizes, int n_in,
                              void* d_out, int out_size)
{
    const float* x  = (const float*)d_in[0];
    const float* W1 = (const float*)d_in[1];
    const float* b1 = (const float*)d_in[2];
    const float* W2 = (const float*)d_in[3];
    const float* b2 = (const float*)d_in[4];
    float* out = (float*)d_out;

    int rows    = in_sizes[0] / 3;       // 8388608
    int ngroups = rows / 4;              // rows is a multiple of 4 here
    int total_threads = (ngroups + 3) / 4;   // 4 groups (16 rows) per thread
    int block = 256;
    int grid  = (total_threads + block - 1) / block;

    node_rk4_kernel<<<grid, block>>>(x, W1, b1, W2, b2, out, ngroups);
}